// round 9
// baseline (speedup 1.0000x reference)
#include <cuda_runtime.h>
#include <cuda_fp16.h>
#include <math.h>

#define HH 192
#define WW 192
#define OH 182
#define OW 182
#define OHW (OH*OW)
#define NB 8
#define NC 64
#define NF 3

#define SSIM_C1 0.01f
#define SSIM_C2 0.09f

// 11-tap gaussian (sigma=1.5), normalized; fp32 literals keep FFMA-imm forms.
#define GW0 0.00102838f
#define GW1 0.00759876f
#define GW2 0.03600077f
#define GW3 0.10936069f
#define GW4 0.21300554f
#define GW5 0.26601173f

#define TAPS(M) M(0,GW0) M(1,GW1) M(2,GW2) M(3,GW3) M(4,GW4) M(5,GW5) \
                M(6,GW4) M(7,GW3) M(8,GW2) M(9,GW1) M(10,GW0)

// __device__ scratch (allocation-free rule)
__device__ float2 g_mf  [NB*NF*OH*OW];   // {mu_f, sig_f}
__device__ float  g_ssim[NB*NF*NC];      // ssim sums (written once per launch)

// ---------------------------------------------------------------------------
// Kernel 1: per-(b,f) gaussian moments {mu_f, sig_f}. Grid (14 strips, 24 ch).
// ---------------------------------------------------------------------------
__global__ void __launch_bounds__(192) f_moments_kernel(const float* __restrict__ f)
{
    const int s   = blockIdx.x;
    const int bj  = blockIdx.y;
    const int tid = threadIdx.x;
    const float* fp = f + (size_t)bj * HH * WW;
    const int o0   = s * 13;
    const int o1   = min(OH, o0 + 13);
    const int rend = o1 + 9;

    __shared__ float2 sp[2][192];
    float a0[11], a1[11];
#pragma unroll
    for (int i = 0; i < 11; ++i) { a0[i] = 0.f; a1[i] = 0.f; }

    float fv = fp[o0 * WW + tid];
    for (int r = o0; r <= rend; ++r) {
        const int buf = r & 1;
        sp[buf][tid] = make_float2(fv, fv * fv);
        float nfv = 0.f;
        if (r < rend) nfv = fp[(r + 1) * WW + tid];
        __syncthreads();
        if (tid < OW) {
            const float2* spb = sp[buf];
            float h0 = 0.f, h1 = 0.f;
#define K1H(k, GK) { float2 q = spb[tid + (k)]; h0 = fmaf((GK), q.x, h0); h1 = fmaf((GK), q.y, h1); }
            TAPS(K1H)
#undef K1H
#pragma unroll
            for (int j = 10; j >= 1; --j) { a0[j] = a0[j-1]; a1[j] = a1[j-1]; }
            a0[0] = 0.f; a1[0] = 0.f;
#define K1A(j, GJ) { a0[j] = fmaf((GJ), h0, a0[j]); a1[j] = fmaf((GJ), h1, a1[j]); }
            TAPS(K1A)
#undef K1A
            if (r - 10 >= o0) {
                const int o = r - 10;
                const float mu = a0[10];
                g_mf[bj * OHW + o * OW + tid] = make_float2(mu, a1[10] - mu * mu);
            }
        }
        fv = nfv;
    }
}

// ---------------------------------------------------------------------------
// Kernel 2: main SSIM (R8 topology, single strip, leaner X staging).
// Grid 512: blockIdx.x = b*64+c; each block does all 192 input rows.
// Team X (tid<192): stages raw x as half (2B), converts + squares in fp32,
//   publishes {mu_x, sig_x}. Team F: stages {f0x,f1x | f2x,0} as half4, HFMA2
//   h-accumulate, v-rings fp32, consumes SSIM with one-row lag.
// One __syncthreads per row.
// ---------------------------------------------------------------------------

struct alignas(8) H4 { __half2 q, r; };

// ring slot for output row (q - t), PH = within-strip phase mod 11
#define RS(PH,t) (((PH) + 22 - (t)) % 11)

#define XT(k,G) { const float q = __half2float(bp[c + (k)]); \
    h0 = fmaf((G), q, h0); h1 = fmaf((G), q*q, h1); }

#define FT(k,WH) { H4 t4 = bp[c + (k)]; \
    hq = __hfma2((WH), t4.q, hq); hr = __hfma2((WH), t4.r, hr); }

#define _XV(PH,t,G,W) { if (!(W) || (PH) >= (t)) { \
    ringA[RS(PH,t)] = fmaf((G), h0, ringA[RS(PH,t)]); \
    ringB[RS(PH,t)] = fmaf((G), h1, ringB[RS(PH,t)]); } }

#define _FV(PH,t,G,W) { if (!(W) || (PH) >= (t)) { \
    ringA[RS(PH,t)] = fmaf((G), h2, ringA[RS(PH,t)]); \
    ringB[RS(PH,t)] = fmaf((G), h3, ringB[RS(PH,t)]); \
    ringD[RS(PH,t)] = fmaf((G), h4, ringD[RS(PH,t)]); } }

#define XV(PH,W) _XV(PH,0,GW0,W) _XV(PH,1,GW1,W) _XV(PH,2,GW2,W) _XV(PH,3,GW3,W) \
                 _XV(PH,4,GW4,W) _XV(PH,5,GW5,W) _XV(PH,6,GW4,W) _XV(PH,7,GW3,W) \
                 _XV(PH,8,GW2,W) _XV(PH,9,GW1,W) _XV(PH,10,GW0,W)
#define FV(PH,W) _FV(PH,0,GW0,W) _FV(PH,1,GW1,W) _FV(PH,2,GW2,W) _FV(PH,3,GW3,W) \
                 _FV(PH,4,GW4,W) _FV(PH,5,GW5,W) _FV(PH,6,GW4,W) _FV(PH,7,GW3,W) \
                 _FV(PH,8,GW2,W) _FV(PH,9,GW1,W) _FV(PH,10,GW0,W)

#define SSJ(MU,SG,P,S) { \
    const float mm  = (MU) * mux; \
    const float num = (2.f*mm + SSIM_C1) * (2.f*((P) - mm) + SSIM_C2); \
    const float den = (fmaf((MU),(MU),mux2) + SSIM_C1) * ((SG) + c2s); \
    S += __fdividef(num, den); }

#define ROW(PH, WARMF) { \
    const int r = rbase + (PH); \
    if (r < HH) { \
        const int buf = r & 1; \
        if (isX) { \
            sP[buf][c] = __float2half_rn(v0); \
            n0 = 0.f; \
            if (r + 1 < HH) n0 = xp[(r+1)*WW + c]; \
        } else { \
            H4 st; st.q = __floats2half2_rn(v1*v0, v2*v0); \
            st.r = __floats2half2_rn(v3*v0, 0.f); \
            sF[buf][c] = st; \
            n0 = 0.f; n1 = 0.f; n2 = 0.f; n3 = 0.f; \
            if (r + 1 < HH) { const int no = (r+1)*WW + c; \
                n0 = xp[no]; n1 = fq0[no]; n2 = fq1[no]; n3 = fq2[no]; } \
            if ((!(WARMF) || (PH) >= 10) && c < OW) { \
                const int mbase = (r-10)*OW + c; \
                nm0 = g_mf[mb0+mbase]; nm1 = g_mf[mb1+mbase]; nm2 = g_mf[mb2+mbase]; } \
        } \
        __syncthreads(); \
        if (c < OW) { \
            if (isX) { \
                float h0 = 0.f, h1 = 0.f; \
                { const __half* bp = sP[buf]; TAPS(XT) } \
                XV(PH, WARMF) \
                if (!(WARMF) || (PH) == 10) { \
                    const int e = ((PH)+1) % 11; \
                    const float mu = ringA[e]; \
                    sex[buf][c] = make_float2(mu, ringB[e] - mu*mu); \
                    ringA[e] = 0.f; ringB[e] = 0.f; } \
            } else { \
                __half2 hq = __float2half2_rn(0.f), hr = hq; \
                { const H4* bp = sF[buf]; \
                  FT(0,W0h) FT(1,W1h) FT(2,W2h) FT(3,W3h) FT(4,W4h) FT(5,W5h) \
                  FT(6,W4h) FT(7,W3h) FT(8,W2h) FT(9,W1h) FT(10,W0h) } \
                const float2 q01 = __half22float2(hq); \
                const float h2 = q01.x, h3 = q01.y, h4 = __low2float(hr); \
                FV(PH, WARMF) \
                if (!(WARMF)) { \
                    const float2 ex = sex[buf ^ 1][c]; \
                    const float mux = ex.x, mux2 = ex.x*ex.x, c2s = ex.y + SSIM_C2; \
                    SSJ(m0.x, m0.y, p0, s0) \
                    SSJ(m1.x, m1.y, p1, s1) \
                    SSJ(m2.x, m2.y, p2, s2) } \
                if (!(WARMF) || (PH) == 10) { \
                    const int e = ((PH)+1) % 11; \
                    p0 = ringA[e]; p1 = ringB[e]; p2 = ringD[e]; \
                    ringA[e] = 0.f; ringB[e] = 0.f; ringD[e] = 0.f; \
                    m0 = nm0; m1 = nm1; m2 = nm2; } \
            } \
        } \
        if (isX) { v0 = n0; } else { v0 = n0; v1 = n1; v2 = n2; v3 = n3; } \
    } }

__global__ void __launch_bounds__(384, 2) ssim_main_kernel(
    const float* __restrict__ x, const float* __restrict__ f)
{
    const int bc  = blockIdx.x;          // b*64 + c
    const int b   = bc >> 6;
    const int ch  = bc & 63;
    const int tid = threadIdx.x;
    const bool isX = tid < 192;
    const int c   = isX ? tid : tid - 192;

    const float* xp  = x + (size_t)bc * HH * WW;
    const float* fq0 = f + (size_t)(b*3 + 0) * HH * WW;
    const float* fq1 = f + (size_t)(b*3 + 1) * HH * WW;
    const float* fq2 = f + (size_t)(b*3 + 2) * HH * WW;
    const int mb0 = (b*3 + 0) * OHW;
    const int mb1 = (b*3 + 1) * OHW;
    const int mb2 = (b*3 + 2) * OHW;

    __shared__ __half  sP[2][192];       // raw x in fp16
    __shared__ H4      sF[2][192];       // {f0x, f1x | f2x, 0} in fp16
    __shared__ float2  sex[2][192];      // exchange {mu_x, sig_x} (fp32)
    __shared__ float   wredF[6][3];

    const __half2 W0h = __float2half2_rn(GW0), W1h = __float2half2_rn(GW1);
    const __half2 W2h = __float2half2_rn(GW2), W3h = __float2half2_rn(GW3);
    const __half2 W4h = __float2half2_rn(GW4), W5h = __float2half2_rn(GW5);

    // vertical rings (fp32): X uses ringA(x), ringB(x^2); F uses ringA(f0x),
    // ringB(f1x), ringD(f2x)
    float ringA[11], ringB[11], ringD[11];
#pragma unroll
    for (int i = 0; i < 11; ++i) { ringA[i] = 0.f; ringB[i] = 0.f; ringD[i] = 0.f; }

    float v0 = 0.f, v1 = 0.f, v2 = 0.f, v3 = 0.f;
    float n0 = 0.f, n1 = 0.f, n2 = 0.f, n3 = 0.f;
    float p0 = 0.f, p1 = 0.f, p2 = 0.f;
    float2 m0 = make_float2(0.f,0.f), m1 = m0, m2 = m0;
    float2 nm0 = m0, nm1 = m0, nm2 = m0;
    float s0 = 0.f, s1 = 0.f, s2 = 0.f;

    // preload first row
    if (isX) {
        v0 = xp[c];
    } else {
        v0 = xp[c]; v1 = fq0[c]; v2 = fq1[c]; v3 = fq2[c];
    }

    {   // warm-up 11 rows (compile-time pruned ring guards; no SSIM consume)
        const int rbase = 0;
        ROW(0,1) ROW(1,1) ROW(2,1) ROW(3,1) ROW(4,1) ROW(5,1)
        ROW(6,1) ROW(7,1) ROW(8,1) ROW(9,1) ROW(10,1)
    }
    for (int rbase = 11; rbase < HH; rbase += 11) {
        ROW(0,0) ROW(1,0) ROW(2,0) ROW(3,0) ROW(4,0) ROW(5,0)
        ROW(6,0) ROW(7,0) ROW(8,0) ROW(9,0) ROW(10,0)
    }

    // flush: consume the last pending output row (uses sex written at row 191)
    __syncthreads();
    if (!isX && c < OW) {
        const float2 ex = sex[(HH-1) & 1][c];
        const float mux = ex.x, mux2 = ex.x*ex.x, c2s = ex.y + SSIM_C2;
        SSJ(m0.x, m0.y, p0, s0)
        SSJ(m1.x, m1.y, p1, s1)
        SSJ(m2.x, m2.y, p2, s2)
    }

    // reduce the 3 sums over team F; write result (no atomics, single strip)
    if (!isX) {
        const float inv = 1.0f / (float)(OH * OW);
        float t0 = s0 * inv, t1 = s1 * inv, t2 = s2 * inv;
#pragma unroll
        for (int off = 16; off; off >>= 1) {
            t0 += __shfl_down_sync(0xFFFFFFFFu, t0, off);
            t1 += __shfl_down_sync(0xFFFFFFFFu, t1, off);
            t2 += __shfl_down_sync(0xFFFFFFFFu, t2, off);
        }
        const int fw = (tid - 192) >> 5, lane = tid & 31;
        if (lane == 0) { wredF[fw][0] = t0; wredF[fw][1] = t1; wredF[fw][2] = t2; }
    }
    __syncthreads();
    if (tid == 192) {
        float q0 = 0.f, q1 = 0.f, q2 = 0.f;
#pragma unroll
        for (int w = 0; w < 6; ++w) { q0 += wredF[w][0]; q1 += wredF[w][1]; q2 += wredF[w][2]; }
        g_ssim[(b*3 + 0)*NC + ch] = q0;
        g_ssim[(b*3 + 1)*NC + ch] = q1;
        g_ssim[(b*3 + 2)*NC + ch] = q2;
    }
}

// ---------------------------------------------------------------------------
// Kernel 3: emit ssim_info to out[512:2048]; spatial gate conv (3,1) over C,
// relu, MLP 64->64->64 (float4 weight loads), sigmoid -> out[0:512].
// ---------------------------------------------------------------------------
__global__ void __launch_bounds__(64) epilogue_kernel(
    const float* __restrict__ sw,
    const float* __restrict__ W1, const float* __restrict__ b1,
    const float* __restrict__ W2, const float* __restrict__ b2,
    float* __restrict__ out, int out_size)
{
    const int b = blockIdx.x;
    const int c = threadIdx.x;

    __shared__ float ss[3][66];     // zero-padded ssim_info for this b
    __shared__ float gate[64];
    __shared__ float h1s[64];

#pragma unroll
    for (int j = 0; j < 3; ++j) {
        const float sj = g_ssim[(b*3 + j)*NC + c];
        ss[j][c + 1] = sj;
        if (out_size >= 2048) out[512 + b*NF*NC + j*NC + c] = sj;
        if (c == 0)  ss[j][0]  = 0.f;
        if (c == 63) ss[j][65] = 0.f;
    }
    __syncthreads();

    float g = 0.f;
#pragma unroll
    for (int j = 0; j < 3; ++j)
#pragma unroll
        for (int d = 0; d < 3; ++d)
            g = fmaf(sw[j*3 + d], ss[j][c + d], g);
    gate[c] = fmaxf(g, 0.f);
    __syncthreads();

    const float4* W1v = reinterpret_cast<const float4*>(W1);
    float h1 = b1[c];
#pragma unroll
    for (int k = 0; k < 16; ++k) {
        const float4 w = W1v[c*16 + k];
        h1 = fmaf(w.x, gate[4*k+0], h1); h1 = fmaf(w.y, gate[4*k+1], h1);
        h1 = fmaf(w.z, gate[4*k+2], h1); h1 = fmaf(w.w, gate[4*k+3], h1);
    }
    h1s[c] = fmaxf(h1, 0.f);
    __syncthreads();

    const float4* W2v = reinterpret_cast<const float4*>(W2);
    float h2 = b2[c];
#pragma unroll
    for (int k = 0; k < 16; ++k) {
        const float4 w = W2v[c*16 + k];
        h2 = fmaf(w.x, h1s[4*k+0], h2); h2 = fmaf(w.y, h1s[4*k+1], h2);
        h2 = fmaf(w.z, h1s[4*k+2], h2); h2 = fmaf(w.w, h1s[4*k+3], h2);
    }
    out[b*64 + c] = 1.0f / (1.0f + expf(-h2));
}

// ---------------------------------------------------------------------------
extern "C" void kernel_launch(void* const* d_in, const int* in_sizes, int n_in,
                              void* d_out, int out_size)
{
    const float* x  = (const float*)d_in[0];
    const float* f  = (const float*)d_in[1];
    const float* sw = (const float*)d_in[2];
    const float* W1 = (const float*)d_in[3];
    const float* b1 = (const float*)d_in[4];
    const float* W2 = (const float*)d_in[5];
    const float* b2 = (const float*)d_in[6];
    float* out = (float*)d_out;

    f_moments_kernel<<<dim3(14, 24), 192>>>(f);
    ssim_main_kernel<<<NB*NC, 384>>>(x, f);
    epilogue_kernel<<<NB, 64>>>(sw, W1, b1, W2, b2, out, out_size);
}

// round 11
// speedup vs baseline: 1.1720x; 1.1720x over previous
#include <cuda_runtime.h>
#include <cuda_fp16.h>
#include <math.h>

#define HH 192
#define WW 192
#define OH 182
#define OW 182
#define OHW (OH*OW)
#define NB 8
#define NC 64
#define NF 3

#define SSIM_C1 0.01f
#define SSIM_C2 0.09f

// 11-tap gaussian (sigma=1.5), normalized; fp32 literals keep FFMA-imm forms.
#define GW0 0.00102838f
#define GW1 0.00759876f
#define GW2 0.03600077f
#define GW3 0.10936069f
#define GW4 0.21300554f
#define GW5 0.26601173f

#define TAPS(M) M(0,GW0) M(1,GW1) M(2,GW2) M(3,GW3) M(4,GW4) M(5,GW5) \
                M(6,GW4) M(7,GW3) M(8,GW2) M(9,GW1) M(10,GW0)

// __device__ scratch (allocation-free rule)
__device__ float2 g_mf [NB*NF*OH*OW];    // {mu_f, sig_f}
__device__ float  g_part[2][NB*NF*NC];   // per-strip ssim partial sums

// ---------------------------------------------------------------------------
// Kernel 1: per-(b,f) gaussian moments {mu_f, sig_f}. Grid (14 strips, 24 ch).
// ---------------------------------------------------------------------------
__global__ void __launch_bounds__(192) f_moments_kernel(const float* __restrict__ f)
{
    const int s   = blockIdx.x;
    const int bj  = blockIdx.y;
    const int tid = threadIdx.x;
    const float* fp = f + (size_t)bj * HH * WW;
    const int o0   = s * 13;
    const int o1   = min(OH, o0 + 13);
    const int rend = o1 + 9;

    __shared__ float2 sp[2][192];
    float a0[11], a1[11];
#pragma unroll
    for (int i = 0; i < 11; ++i) { a0[i] = 0.f; a1[i] = 0.f; }

    float fv = fp[o0 * WW + tid];
    for (int r = o0; r <= rend; ++r) {
        const int buf = r & 1;
        sp[buf][tid] = make_float2(fv, fv * fv);
        float nfv = 0.f;
        if (r < rend) nfv = fp[(r + 1) * WW + tid];
        __syncthreads();
        if (tid < OW) {
            const float2* spb = sp[buf];
            float h0 = 0.f, h1 = 0.f;
#define K1H(k, GK) { float2 q = spb[tid + (k)]; h0 = fmaf((GK), q.x, h0); h1 = fmaf((GK), q.y, h1); }
            TAPS(K1H)
#undef K1H
#pragma unroll
            for (int j = 10; j >= 1; --j) { a0[j] = a0[j-1]; a1[j] = a1[j-1]; }
            a0[0] = 0.f; a1[0] = 0.f;
#define K1A(j, GJ) { a0[j] = fmaf((GJ), h0, a0[j]); a1[j] = fmaf((GJ), h1, a1[j]); }
            TAPS(K1A)
#undef K1A
            if (r - 10 >= o0) {
                const int o = r - 10;
                const float mu = a0[10];
                g_mf[bj * OHW + o * OW + tid] = make_float2(mu, a1[10] - mu * mu);
            }
        }
        fv = nfv;
    }
}

// ---------------------------------------------------------------------------
// Kernel 2: main SSIM (R8 topology exactly; X stages raw half x = 2 B/tap).
// Grid (512, 2): blockIdx.x = b*64+c, blockIdx.y = row strip (91 out rows).
// Team X (tid<192): stages raw x as half, converts once + squares in fp32,
//   publishes {mu_x, sig_x}. Team F: stages {f0x,f1x | f2x,0} as half4, HFMA2
//   h-accumulate, v-rings fp32, consumes SSIM with one-row lag.
// One __syncthreads per row.
// ---------------------------------------------------------------------------

struct alignas(8) H4 { __half2 q, r; };

// ring slot for output row (q - t), PH = within-strip phase mod 11
#define RS(PH,t) (((PH) + 22 - (t)) % 11)

#define XT(k,G) { const float q = __half2float(bp[c + (k)]); \
    h0 = fmaf((G), q, h0); h1 = fmaf((G), q*q, h1); }

#define FT(k,WH) { H4 t4 = bp[c + (k)]; \
    hq = __hfma2((WH), t4.q, hq); hr = __hfma2((WH), t4.r, hr); }

#define _XV(PH,t,G,W) { if (!(W) || (PH) >= (t)) { \
    ringA[RS(PH,t)] = fmaf((G), h0, ringA[RS(PH,t)]); \
    ringB[RS(PH,t)] = fmaf((G), h1, ringB[RS(PH,t)]); } }

#define _FV(PH,t,G,W) { if (!(W) || (PH) >= (t)) { \
    ringA[RS(PH,t)] = fmaf((G), h2, ringA[RS(PH,t)]); \
    ringB[RS(PH,t)] = fmaf((G), h3, ringB[RS(PH,t)]); \
    ringD[RS(PH,t)] = fmaf((G), h4, ringD[RS(PH,t)]); } }

#define XV(PH,W) _XV(PH,0,GW0,W) _XV(PH,1,GW1,W) _XV(PH,2,GW2,W) _XV(PH,3,GW3,W) \
                 _XV(PH,4,GW4,W) _XV(PH,5,GW5,W) _XV(PH,6,GW4,W) _XV(PH,7,GW3,W) \
                 _XV(PH,8,GW2,W) _XV(PH,9,GW1,W) _XV(PH,10,GW0,W)
#define FV(PH,W) _FV(PH,0,GW0,W) _FV(PH,1,GW1,W) _FV(PH,2,GW2,W) _FV(PH,3,GW3,W) \
                 _FV(PH,4,GW4,W) _FV(PH,5,GW5,W) _FV(PH,6,GW4,W) _FV(PH,7,GW3,W) \
                 _FV(PH,8,GW2,W) _FV(PH,9,GW1,W) _FV(PH,10,GW0,W)

#define SSJ(MU,SG,P,S) { \
    const float mm  = (MU) * mux; \
    const float num = (2.f*mm + SSIM_C1) * (2.f*((P) - mm) + SSIM_C2); \
    const float den = (fmaf((MU),(MU),mux2) + SSIM_C1) * ((SG) + c2s); \
    S += __fdividef(num, den); }

#define ROW(PH, WARMF) { \
    const int r = rbase + (PH); \
    if (r < rend) { \
        const int buf = r & 1; \
        if (isX) { \
            sP[buf][c] = __float2half_rn(v0); \
            n0 = 0.f; \
            if (r + 1 < rend) n0 = xp[(r+1)*WW + c]; \
        } else { \
            H4 st; st.q = __floats2half2_rn(v1*v0, v2*v0); \
            st.r = __floats2half2_rn(v3*v0, 0.f); \
            sF[buf][c] = st; \
            n0 = 0.f; n1 = 0.f; n2 = 0.f; n3 = 0.f; \
            if (r + 1 < rend) { const int no = (r+1)*WW + c; \
                n0 = xp[no]; n1 = fq0[no]; n2 = fq1[no]; n3 = fq2[no]; } \
            if ((!(WARMF) || (PH) >= 10) && c < OW) { \
                const int mbase = (r-10)*OW + c; \
                nm0 = g_mf[mb0+mbase]; nm1 = g_mf[mb1+mbase]; nm2 = g_mf[mb2+mbase]; } \
        } \
        __syncthreads(); \
        if (c < OW) { \
            if (isX) { \
                float h0 = 0.f, h1 = 0.f; \
                { const __half* bp = sP[buf]; TAPS(XT) } \
                XV(PH, WARMF) \
                if (!(WARMF) || (PH) == 10) { \
                    const int e = ((PH)+1) % 11; \
                    const float mu = ringA[e]; \
                    sex[buf][c] = make_float2(mu, ringB[e] - mu*mu); \
                    ringA[e] = 0.f; ringB[e] = 0.f; } \
            } else { \
                __half2 hq = __float2half2_rn(0.f), hr = hq; \
                { const H4* bp = sF[buf]; \
                  FT(0,W0h) FT(1,W1h) FT(2,W2h) FT(3,W3h) FT(4,W4h) FT(5,W5h) \
                  FT(6,W4h) FT(7,W3h) FT(8,W2h) FT(9,W1h) FT(10,W0h) } \
                const float2 q01 = __half22float2(hq); \
                const float h2 = q01.x, h3 = q01.y, h4 = __low2float(hr); \
                FV(PH, WARMF) \
                if (!(WARMF)) { \
                    const float2 ex = sex[buf ^ 1][c]; \
                    const float mux = ex.x, mux2 = ex.x*ex.x, c2s = ex.y + SSIM_C2; \
                    SSJ(m0.x, m0.y, p0, s0) \
                    SSJ(m1.x, m1.y, p1, s1) \
                    SSJ(m2.x, m2.y, p2, s2) } \
                if (!(WARMF) || (PH) == 10) { \
                    const int e = ((PH)+1) % 11; \
                    p0 = ringA[e]; p1 = ringB[e]; p2 = ringD[e]; \
                    ringA[e] = 0.f; ringB[e] = 0.f; ringD[e] = 0.f; \
                    m0 = nm0; m1 = nm1; m2 = nm2; } \
            } \
        } \
        if (isX) { v0 = n0; } else { v0 = n0; v1 = n1; v2 = n2; v3 = n3; } \
    } }

__global__ void __launch_bounds__(384, 2) ssim_main_kernel(
    const float* __restrict__ x, const float* __restrict__ f)
{
    const int bc  = blockIdx.x;          // b*64 + c
    const int b   = bc >> 6;
    const int ch  = bc & 63;
    const int tid = threadIdx.x;
    const bool isX = tid < 192;
    const int c   = isX ? tid : tid - 192;

    const int r0s  = blockIdx.y * 91;    // strip input start
    const int rend = r0s + 101;          // strip input end (exclusive)

    const float* xp  = x + (size_t)bc * HH * WW;
    const float* fq0 = f + (size_t)(b*3 + 0) * HH * WW;
    const float* fq1 = f + (size_t)(b*3 + 1) * HH * WW;
    const float* fq2 = f + (size_t)(b*3 + 2) * HH * WW;
    const int mb0 = (b*3 + 0) * OHW;
    const int mb1 = (b*3 + 1) * OHW;
    const int mb2 = (b*3 + 2) * OHW;

    __shared__ __half  sP[2][192];       // raw x in fp16 (2 B/tap)
    __shared__ H4      sF[2][192];       // {f0x, f1x | f2x, 0} in fp16
    __shared__ float2  sex[2][192];      // exchange {mu_x, sig_x} (fp32)
    __shared__ float   wredF[6][3];

    const __half2 W0h = __float2half2_rn(GW0), W1h = __float2half2_rn(GW1);
    const __half2 W2h = __float2half2_rn(GW2), W3h = __float2half2_rn(GW3);
    const __half2 W4h = __float2half2_rn(GW4), W5h = __float2half2_rn(GW5);

    // vertical rings (fp32): X uses ringA(x), ringB(x^2); F uses ringA(f0x),
    // ringB(f1x), ringD(f2x)
    float ringA[11], ringB[11], ringD[11];
#pragma unroll
    for (int i = 0; i < 11; ++i) { ringA[i] = 0.f; ringB[i] = 0.f; ringD[i] = 0.f; }

    float v0 = 0.f, v1 = 0.f, v2 = 0.f, v3 = 0.f;
    float n0 = 0.f, n1 = 0.f, n2 = 0.f, n3 = 0.f;
    float p0 = 0.f, p1 = 0.f, p2 = 0.f;
    float2 m0 = make_float2(0.f,0.f), m1 = m0, m2 = m0;
    float2 nm0 = m0, nm1 = m0, nm2 = m0;
    float s0 = 0.f, s1 = 0.f, s2 = 0.f;

    // preload strip first row
    if (isX) {
        v0 = xp[r0s*WW + c];
    } else {
        const int o = r0s*WW + c;
        v0 = xp[o]; v1 = fq0[o]; v2 = fq1[o]; v3 = fq2[o];
    }

    {   // warm-up 11 rows (compile-time pruned ring guards; no SSIM consume)
        const int rbase = r0s;
        ROW(0,1) ROW(1,1) ROW(2,1) ROW(3,1) ROW(4,1) ROW(5,1)
        ROW(6,1) ROW(7,1) ROW(8,1) ROW(9,1) ROW(10,1)
    }
    for (int rbase = r0s + 11; rbase < rend; rbase += 11) {
        ROW(0,0) ROW(1,0) ROW(2,0) ROW(3,0) ROW(4,0) ROW(5,0)
        ROW(6,0) ROW(7,0) ROW(8,0) ROW(9,0) ROW(10,0)
    }

    // flush: consume the last pending output row (uses sex written at rend-1)
    __syncthreads();
    if (!isX && c < OW) {
        const float2 ex = sex[(rend-1) & 1][c];
        const float mux = ex.x, mux2 = ex.x*ex.x, c2s = ex.y + SSIM_C2;
        SSJ(m0.x, m0.y, p0, s0)
        SSJ(m1.x, m1.y, p1, s1)
        SSJ(m2.x, m2.y, p2, s2)
    }

    // reduce the 3 sums over team F; write per-strip partial (no atomics)
    if (!isX) {
        const float inv = 1.0f / (float)(OH * OW);
        float t0 = s0 * inv, t1 = s1 * inv, t2 = s2 * inv;
#pragma unroll
        for (int off = 16; off; off >>= 1) {
            t0 += __shfl_down_sync(0xFFFFFFFFu, t0, off);
            t1 += __shfl_down_sync(0xFFFFFFFFu, t1, off);
            t2 += __shfl_down_sync(0xFFFFFFFFu, t2, off);
        }
        const int fw = (tid - 192) >> 5, lane = tid & 31;
        if (lane == 0) { wredF[fw][0] = t0; wredF[fw][1] = t1; wredF[fw][2] = t2; }
    }
    __syncthreads();
    if (tid == 192) {
        float q0 = 0.f, q1 = 0.f, q2 = 0.f;
#pragma unroll
        for (int w = 0; w < 6; ++w) { q0 += wredF[w][0]; q1 += wredF[w][1]; q2 += wredF[w][2]; }
        g_part[blockIdx.y][(b*3 + 0)*NC + ch] = q0;
        g_part[blockIdx.y][(b*3 + 1)*NC + ch] = q1;
        g_part[blockIdx.y][(b*3 + 2)*NC + ch] = q2;
    }
}

// ---------------------------------------------------------------------------
// Kernel 3: sum strip partials; emit ssim_info to out[512:2048]; spatial gate
// conv (3,1) over C, relu, MLP 64->64->64 (float4 weight loads), sigmoid.
// ---------------------------------------------------------------------------
__global__ void __launch_bounds__(64) epilogue_kernel(
    const float* __restrict__ sw,
    const float* __restrict__ W1, const float* __restrict__ b1,
    const float* __restrict__ W2, const float* __restrict__ b2,
    float* __restrict__ out, int out_size)
{
    const int b = blockIdx.x;
    const int c = threadIdx.x;

    __shared__ float ss[3][66];     // zero-padded ssim_info for this b
    __shared__ float gate[64];
    __shared__ float h1s[64];

#pragma unroll
    for (int j = 0; j < 3; ++j) {
        const int idx = (b*3 + j)*NC + c;
        const float sj = g_part[0][idx] + g_part[1][idx];
        ss[j][c + 1] = sj;
        if (out_size >= 2048) out[512 + b*NF*NC + j*NC + c] = sj;
        if (c == 0)  ss[j][0]  = 0.f;
        if (c == 63) ss[j][65] = 0.f;
    }
    __syncthreads();

    float g = 0.f;
#pragma unroll
    for (int j = 0; j < 3; ++j)
#pragma unroll
        for (int d = 0; d < 3; ++d)
            g = fmaf(sw[j*3 + d], ss[j][c + d], g);
    gate[c] = fmaxf(g, 0.f);
    __syncthreads();

    const float4* W1v = reinterpret_cast<const float4*>(W1);
    float h1 = b1[c];
#pragma unroll
    for (int k = 0; k < 16; ++k) {
        const float4 w = W1v[c*16 + k];
        h1 = fmaf(w.x, gate[4*k+0], h1); h1 = fmaf(w.y, gate[4*k+1], h1);
        h1 = fmaf(w.z, gate[4*k+2], h1); h1 = fmaf(w.w, gate[4*k+3], h1);
    }
    h1s[c] = fmaxf(h1, 0.f);
    __syncthreads();

    const float4* W2v = reinterpret_cast<const float4*>(W2);
    float h2 = b2[c];
#pragma unroll
    for (int k = 0; k < 16; ++k) {
        const float4 w = W2v[c*16 + k];
        h2 = fmaf(w.x, h1s[4*k+0], h2); h2 = fmaf(w.y, h1s[4*k+1], h2);
        h2 = fmaf(w.z, h1s[4*k+2], h2); h2 = fmaf(w.w, h1s[4*k+3], h2);
    }
    out[b*64 + c] = 1.0f / (1.0f + expf(-h2));
}

// ---------------------------------------------------------------------------
extern "C" void kernel_launch(void* const* d_in, const int* in_sizes, int n_in,
                              void* d_out, int out_size)
{
    const float* x  = (const float*)d_in[0];
    const float* f  = (const float*)d_in[1];
    const float* sw = (const float*)d_in[2];
    const float* W1 = (const float*)d_in[3];
    const float* b1 = (const float*)d_in[4];
    const float* W2 = (const float*)d_in[5];
    const float* b2 = (const float*)d_in[6];
    float* out = (float*)d_out;

    f_moments_kernel<<<dim3(14, 24), 192>>>(f);
    ssim_main_kernel<<<dim3(NB*NC, 2), 384>>>(x, f);
    epilogue_kernel<<<NB, 64>>>(sw, W1, b1, W2, b2, out, out_size);
}